// round 8
// baseline (speedup 1.0000x reference)
#include <cuda_runtime.h>
#include <cuda_bf16.h>
#include <cstdint>

// ---------------------------------------------------------------------------
// b=4, n=8192, dim=512, h=8, w=256, d=64.  T=32768 tokens, 128 windows.
// All matmuls: mma.sync bf16, hi/lo 3-product split, fp32 accumulate.
// Round 8: MMA emission reordered (frags loaded up-front, products grouped
// hh/hl/lh) so dependent HMMAs to the same accumulator sit >=16 MMAs apart.
// ---------------------------------------------------------------------------

__device__ __nv_bfloat16  g_qkvhi[32768ull * 1536], g_qkvlo[32768ull * 1536];
__device__ __nv_bfloat16  g_xhi[32768ull * 512],  g_xlo[32768ull * 512];
__device__ __nv_bfloat16  g_ahi[32768ull * 512],  g_alo[32768ull * 512];
__device__ __nv_bfloat16  g_wqhi[1536ull * 512],  g_wqlo[1536ull * 512];
__device__ __nv_bfloat16  g_wphi[512ull * 512],   g_wplo[512ull * 512];

#define NPERSIST 148

// ---------------- helpers ---------------------------------------------------
__device__ __forceinline__ uint32_t smem_u32(const void* p) {
    uint32_t a;
    asm("{ .reg .u64 t; cvta.to.shared.u64 t, %1; cvt.u32.u64 %0, t; }"
        : "=r"(a) : "l"(p));
    return a;
}
#define SWZ128(x) ((x) ^ (((x) >> 3) & 0x70))

__device__ __forceinline__ void cpa16(uint32_t dst, const void* src) {
    asm volatile("cp.async.cg.shared.global [%0], [%1], 16;"
                 :: "r"(dst), "l"(src) : "memory");
}
template <int N>
__device__ __forceinline__ void cp_wait() {
    asm volatile("cp.async.wait_group %0;" :: "n"(N) : "memory");
}

#define LDSM_X4(r, addr)                                                      \
    asm volatile("ldmatrix.sync.aligned.m8n8.x4.shared.b16 {%0,%1,%2,%3}, [%4];" \
                 : "=r"((r)[0]), "=r"((r)[1]), "=r"((r)[2]), "=r"((r)[3])     \
                 : "r"(addr))

#define MMA_BF16(d, a, b0, b1)                                                \
    asm volatile("mma.sync.aligned.m16n8k16.row.col.f32.bf16.bf16.f32 "       \
                 "{%0,%1,%2,%3}, {%4,%5,%6,%7}, {%8,%9}, {%0,%1,%2,%3};"      \
                 : "+f"((d)[0]), "+f"((d)[1]), "+f"((d)[2]), "+f"((d)[3])     \
                 : "r"((a)[0]), "r"((a)[1]), "r"((a)[2]), "r"((a)[3]),        \
                   "r"(b0), "r"(b1))

__device__ __forceinline__ uint32_t bf16x2_pack(float lo, float hi) {
    uint32_t r;
    asm("cvt.rn.bf16x2.f32 %0, %1, %2;" : "=r"(r) : "f"(hi), "f"(lo));
    return r;
}

// ---------------------------------------------------------------------------
__global__ void split_kernel(const float* __restrict__ in,
                             __nv_bfloat16* __restrict__ hi,
                             __nv_bfloat16* __restrict__ lo, int n4)
{
    int i = blockIdx.x * blockDim.x + threadIdx.x;
    if (i >= n4) return;
    float4 v = ((const float4*)in)[i];
    __nv_bfloat16 h0 = __float2bfloat16(v.x), h1 = __float2bfloat16(v.y);
    __nv_bfloat16 h2 = __float2bfloat16(v.z), h3 = __float2bfloat16(v.w);
    __nv_bfloat16 l0 = __float2bfloat16(v.x - __bfloat162float(h0));
    __nv_bfloat16 l1 = __float2bfloat16(v.y - __bfloat162float(h1));
    __nv_bfloat16 l2 = __float2bfloat16(v.z - __bfloat162float(h2));
    __nv_bfloat16 l3 = __float2bfloat16(v.w - __bfloat162float(h3));
    __nv_bfloat162* hp = (__nv_bfloat162*)(hi + (size_t)i * 4);
    __nv_bfloat162* lp = (__nv_bfloat162*)(lo + (size_t)i * 4);
    hp[0] = {h0, h1}; hp[1] = {h2, h3};
    lp[0] = {l0, l1}; lp[1] = {l2, l3};
}

__global__ void tsplit_kernel(const float* __restrict__ W,
                              __nv_bfloat16* __restrict__ thi,
                              __nv_bfloat16* __restrict__ tlo, int K, int N)
{
    __shared__ float t[32][33];
    const int kx = blockIdx.y * 32, nx = blockIdx.x * 32;
    const int lx = threadIdx.x & 31, ly = threadIdx.x >> 5;
#pragma unroll
    for (int j = 0; j < 32; j += 8)
        t[ly + j][lx] = W[(size_t)(kx + ly + j) * N + nx + lx];
    __syncthreads();
#pragma unroll
    for (int j = 0; j < 32; j += 8) {
        float v = t[lx][ly + j];
        __nv_bfloat16 h = __float2bfloat16(v);
        __nv_bfloat16 l = __float2bfloat16(v - __bfloat162float(h));
        thi[(size_t)(nx + ly + j) * K + kx + lx] = h;
        tlo[(size_t)(nx + ly + j) * K + kx + lx] = l;
    }
}

// ---------------------------------------------------------------------------
// Persistent mma.sync GEMM, 256 threads, tile 128x128, warp tile 32x64.
// Inner loop: all 12 ldmatrix first, then 48 MMAs grouped hh/hl/lh.
// ---------------------------------------------------------------------------
#define GK        512
#define KC        64
#define CPT       (GK / KC)
#define STAGE     65536
#define GM_SMEM   (2 * STAGE)

__global__ __launch_bounds__(256, 1)
void gemm_mma(const __nv_bfloat16* __restrict__ Ahi,
              const __nv_bfloat16* __restrict__ Alo,
              const __nv_bfloat16* __restrict__ Bhi,
              const __nv_bfloat16* __restrict__ Blo,
              const float* __restrict__ bias,
              float* __restrict__ Cf,
              __nv_bfloat16* __restrict__ Chi, __nv_bfloat16* __restrict__ Clo,
              int N, int M, int bf16out)
{
    extern __shared__ char sm[];
    const uint32_t sb = smem_u32(sm);
    const int tid = threadIdx.x, wid = tid >> 5, lane = tid & 31;
    const int wm = wid & 3, wn = wid >> 2;

    const int gx = N >> 7;
    const int total_tiles = (M >> 7) * gx;
    const int my_tiles = (total_tiles - blockIdx.x + NPERSIST - 1) / NPERSIST;
    const int total_chunks = my_tiles * CPT;

    auto tile_mn = [&](int tl, int& m0, int& n0) {
        const int tg = blockIdx.x + tl * NPERSIST;
        m0 = (tg / gx) << 7;
        n0 = (tg % gx) << 7;
    };

    auto load_ci = [&](int ci) {
        int m0, n0;
        tile_mn(ci >> 3, m0, n0);
        const int k0 = (ci & 7) * KC;
        const uint32_t base = sb + (ci & 1) * STAGE;
#pragma unroll
        for (int it = 0; it < 4; ++it) {
            const int op = it * 256 + tid;
            const int r = op >> 3, g = op & 7;
            const uint32_t off = SWZ128((uint32_t)(r * 128 + g * 16));
            const size_t giA = (size_t)(m0 + r) * GK + k0 + g * 8;
            const size_t giB = (size_t)(n0 + r) * GK + k0 + g * 8;
            cpa16(base + off,         Ahi + giA);
            cpa16(base + 16384 + off, Alo + giA);
            cpa16(base + 32768 + off, Bhi + giB);
            cpa16(base + 49152 + off, Blo + giB);
        }
        asm volatile("cp.async.commit_group;" ::: "memory");
    };

    float acc[2][8][4];
#pragma unroll
    for (int i = 0; i < 2; ++i)
#pragma unroll
        for (int j = 0; j < 8; ++j)
#pragma unroll
            for (int k = 0; k < 4; ++k) acc[i][j][k] = 0.0f;

    const int a_row = wm * 32 + (lane & 15);
    const int a_kb  = (lane >> 4) * 16;
    const int b_row = wn * 64 + (lane & 7) + ((lane >> 4) << 3);
    const int b_kb  = ((lane >> 3) & 1) * 16;
    const int er = lane >> 2, ec = (lane & 3) * 2;

    if (total_chunks > 0) load_ci(0);
    if (total_chunks > 1) load_ci(1);

    for (int ci = 0; ci < total_chunks; ++ci) {
        if (ci + 1 < total_chunks) cp_wait<1>();
        else                       cp_wait<0>();
        __syncthreads();

        const uint32_t bufb = sb + (ci & 1) * STAGE;
#pragma unroll
        for (int g = 0; g < 4; ++g) {
            // ---- load ALL fragments for this k-group first ----
            uint32_t ah[2][4], al[2][4], bh[4][4], bl[4][4];
#pragma unroll
            for (int mt = 0; mt < 2; ++mt) {
                const uint32_t offA =
                    SWZ128((uint32_t)((a_row + mt * 16) * 128 + g * 32 + a_kb));
                LDSM_X4(ah[mt], bufb + offA);
                LDSM_X4(al[mt], bufb + 16384 + offA);
            }
#pragma unroll
            for (int np = 0; np < 4; ++np) {
                const uint32_t offB =
                    SWZ128((uint32_t)((b_row + np * 16) * 128 + g * 32 + b_kb));
                LDSM_X4(bh[np], bufb + 32768 + offB);
                LDSM_X4(bl[np], bufb + 49152 + offB);
            }
            // ---- MMAs grouped by product: dependent writes 16 apart ----
#pragma unroll
            for (int np = 0; np < 4; ++np)
#pragma unroll
                for (int mt = 0; mt < 2; ++mt) {
                    MMA_BF16(acc[mt][np * 2 + 0], ah[mt], bh[np][0], bh[np][1]);
                    MMA_BF16(acc[mt][np * 2 + 1], ah[mt], bh[np][2], bh[np][3]);
                }
#pragma unroll
            for (int np = 0; np < 4; ++np)
#pragma unroll
                for (int mt = 0; mt < 2; ++mt) {
                    MMA_BF16(acc[mt][np * 2 + 0], ah[mt], bl[np][0], bl[np][1]);
                    MMA_BF16(acc[mt][np * 2 + 1], ah[mt], bl[np][2], bl[np][3]);
                }
#pragma unroll
            for (int np = 0; np < 4; ++np)
#pragma unroll
                for (int mt = 0; mt < 2; ++mt) {
                    MMA_BF16(acc[mt][np * 2 + 0], al[mt], bh[np][0], bh[np][1]);
                    MMA_BF16(acc[mt][np * 2 + 1], al[mt], bh[np][2], bh[np][3]);
                }
        }
        __syncthreads();

        if (ci + 2 < total_chunks) load_ci(ci + 2);

        if ((ci & 7) == 7) {
            int m0, n0;
            tile_mn(ci >> 3, m0, n0);
#pragma unroll
            for (int mt = 0; mt < 2; ++mt) {
                const int row = m0 + wm * 32 + mt * 16 + er;
#pragma unroll
                for (int nt = 0; nt < 8; ++nt) {
                    const int col = n0 + wn * 64 + nt * 8 + ec;
                    const float2 bv = *(const float2*)(bias + col);
                    float v00 = acc[mt][nt][0] + bv.x, v01 = acc[mt][nt][1] + bv.y;
                    float v10 = acc[mt][nt][2] + bv.x, v11 = acc[mt][nt][3] + bv.y;
                    if (bf16out) {
                        __nv_bfloat16 h00 = __float2bfloat16(v00);
                        __nv_bfloat16 h01 = __float2bfloat16(v01);
                        __nv_bfloat16 h10 = __float2bfloat16(v10);
                        __nv_bfloat16 h11 = __float2bfloat16(v11);
                        *(__nv_bfloat162*)(Chi + (size_t)row * N + col)       = {h00, h01};
                        *(__nv_bfloat162*)(Chi + (size_t)(row + 8) * N + col) = {h10, h11};
                        __nv_bfloat162 l0 = {__float2bfloat16(v00 - __bfloat162float(h00)),
                                             __float2bfloat16(v01 - __bfloat162float(h01))};
                        __nv_bfloat162 l1 = {__float2bfloat16(v10 - __bfloat162float(h10)),
                                             __float2bfloat16(v11 - __bfloat162float(h11))};
                        *(__nv_bfloat162*)(Clo + (size_t)row * N + col)       = l0;
                        *(__nv_bfloat162*)(Clo + (size_t)(row + 8) * N + col) = l1;
                    } else {
                        *(float2*)(Cf + (size_t)row * N + col)       = make_float2(v00, v01);
                        *(float2*)(Cf + (size_t)(row + 8) * N + col) = make_float2(v10, v11);
                    }
                    acc[mt][nt][0] = 0.0f; acc[mt][nt][1] = 0.0f;
                    acc[mt][nt][2] = 0.0f; acc[mt][nt][3] = 0.0f;
                }
            }
        }
    }
}

// ---------------------------------------------------------------------------
// Tensor-core block-local attention, MMA emission reordered like the GEMM.
// ---------------------------------------------------------------------------
#define KSTR 72
#define VSTR 264
#define QSTR 72
#define OSTR 68
#define OFF_KHI  0
#define OFF_KLO  36864
#define OFF_VHI  73728
#define OFF_VLO  107520
#define OFF_QHI  141312
#define OFF_QLO  150528
#define OFF_O    159744
#define OFF_PMAX 177152
#define OFF_PSUM 177664
#define ATT2_SMEM 178176

__global__ __launch_bounds__(256, 1)
void attn_mma(const __nv_bfloat16* __restrict__ qkh,
              const __nv_bfloat16* __restrict__ qkl,
              const float* __restrict__ bias,
              __nv_bfloat16* __restrict__ ohi,
              __nv_bfloat16* __restrict__ olo)
{
    extern __shared__ char sm[];
    const uint32_t sb = smem_u32(sm);
    float* Osm  = (float*)(sm + OFF_O);
    float* pmax = (float*)(sm + OFF_PMAX);
    float* psum = (float*)(sm + OFF_PSUM);

    const int tid = threadIdx.x, lane = tid & 31, wid = tid >> 5;
    const int wm = wid & 3, wn = wid >> 2;
    const int head = blockIdx.x & 7, win = blockIdx.x >> 3;
    const int tbase = win * 256;
    const float scale = 0.125f;

#pragma unroll
    for (int it = 0; it < 16; ++it) {
        const int idx = it * 256 + tid;
        const int buf = idx >> 11, rem = idx & 2047;
        const int key = rem >> 3, u = rem & 7;
        const __nv_bfloat16* src = (buf ? qkl : qkh) +
            (size_t)(tbase + key) * 1536 + 512 + head * 64 + u * 8;
        char* dst = sm + (buf ? OFF_KLO : OFF_KHI) + key * (KSTR * 2) + u * 16;
        *(uint4*)dst = *(const uint4*)src;
    }
    {
        const int buf = tid >> 7, p = tid & 127;
        const __nv_bfloat16* s0 = (buf ? qkl : qkh) +
            (size_t)(tbase + 2 * p) * 1536 + 1024 + head * 64;
        const __nv_bfloat16* s1 = s0 + 1536;
        char* vt = sm + (buf ? OFF_VLO : OFF_VHI);
#pragma unroll
        for (int u = 0; u < 8; ++u) {
            const uint4 a = *(const uint4*)(s0 + u * 8);
            const uint4 b = *(const uint4*)(s1 + u * 8);
            const unsigned short* ap = (const unsigned short*)&a;
            const unsigned short* bp = (const unsigned short*)&b;
#pragma unroll
            for (int j = 0; j < 8; ++j) {
                const int d = u * 8 + j;
                *(uint32_t*)(vt + d * (VSTR * 2) + p * 4) =
                    (uint32_t)ap[j] | ((uint32_t)bp[j] << 16);
            }
        }
    }
    __syncthreads();

    const int qa_row = wm * 16 + (lane & 15);
    const int qa_ke  = (lane >> 4) * 8;
    const int kb_rowc = (lane & 7) + ((lane >> 4) << 3);
    const int kb_ke   = ((lane >> 3) & 1) * 8;

    for (int qt = 0; qt < 4; ++qt) {
#pragma unroll
        for (int it = 0; it < 4; ++it) {
            const int idx = it * 256 + tid;
            const int buf = idx >> 9, rem = idx & 511;
            const int row = rem >> 3, u = rem & 7;
            const __nv_bfloat16* src = (buf ? qkl : qkh) +
                (size_t)(tbase + qt * 64 + row) * 1536 + head * 64 + u * 8;
            char* dst = sm + (buf ? OFF_QLO : OFF_QHI) + row * (QSTR * 2) + u * 16;
            *(uint4*)dst = *(const uint4*)src;
        }
        __syncthreads();

        float c[16][4];
#pragma unroll
        for (int i = 0; i < 16; ++i)
#pragma unroll
            for (int j = 0; j < 4; ++j) c[i][j] = 0.0f;

#pragma unroll
        for (int kt = 0; kt < 4; ++kt) {
            uint32_t ah[4], al[4], bh[8][4], bl[8][4];
            const uint32_t offQ =
                (uint32_t)(qa_row * (QSTR * 2) + kt * 32 + qa_ke * 2);
            LDSM_X4(ah, sb + OFF_QHI + offQ);
            LDSM_X4(al, sb + OFF_QLO + offQ);
#pragma unroll
            for (int nt2 = 0; nt2 < 8; ++nt2) {
                const int krow = wn * 128 + nt2 * 16 + kb_rowc;
                const uint32_t offK =
                    (uint32_t)(krow * (KSTR * 2) + kt * 32 + kb_ke * 2);
                LDSM_X4(bh[nt2], sb + OFF_KHI + offK);
                LDSM_X4(bl[nt2], sb + OFF_KLO + offK);
            }
#pragma unroll
            for (int nt2 = 0; nt2 < 8; ++nt2) {
                MMA_BF16(c[nt2 * 2 + 0], ah, bh[nt2][0], bh[nt2][1]);
                MMA_BF16(c[nt2 * 2 + 1], ah, bh[nt2][2], bh[nt2][3]);
            }
#pragma unroll
            for (int nt2 = 0; nt2 < 8; ++nt2) {
                MMA_BF16(c[nt2 * 2 + 0], ah, bl[nt2][0], bl[nt2][1]);
                MMA_BF16(c[nt2 * 2 + 1], ah, bl[nt2][2], bl[nt2][3]);
            }
#pragma unroll
            for (int nt2 = 0; nt2 < 8; ++nt2) {
                MMA_BF16(c[nt2 * 2 + 0], al, bh[nt2][0], bh[nt2][1]);
                MMA_BF16(c[nt2 * 2 + 1], al, bh[nt2][2], bh[nt2][3]);
            }
        }

        const float* bb = bias + head * 65536 +
            (size_t)(qt * 64 + wm * 16 + (lane >> 2)) * 256 +
            wn * 128 + (lane & 3) * 2;
#pragma unroll
        for (int nt = 0; nt < 16; ++nt) {
            const float2 b0 = *(const float2*)(bb + nt * 8);
            const float2 b8 = *(const float2*)(bb + 2048 + nt * 8);
            c[nt][0] = c[nt][0] * scale + b0.x;
            c[nt][1] = c[nt][1] * scale + b0.y;
            c[nt][2] = c[nt][2] * scale + b8.x;
            c[nt][3] = c[nt][3] * scale + b8.y;
        }

        float m0 = c[0][0], m8 = c[0][2];
#pragma unroll
        for (int nt = 0; nt < 16; ++nt) {
            m0 = fmaxf(m0, fmaxf(c[nt][0], c[nt][1]));
            m8 = fmaxf(m8, fmaxf(c[nt][2], c[nt][3]));
        }
        m0 = fmaxf(m0, __shfl_xor_sync(0xffffffffu, m0, 1));
        m0 = fmaxf(m0, __shfl_xor_sync(0xffffffffu, m0, 2));
        m8 = fmaxf(m8, __shfl_xor_sync(0xffffffffu, m8, 1));
        m8 = fmaxf(m8, __shfl_xor_sync(0xffffffffu, m8, 2));
        const int r0 = wm * 16 + (lane >> 2);
        if ((lane & 3) == 0) {
            pmax[wn * 64 + r0]     = m0;
            pmax[wn * 64 + r0 + 8] = m8;
        }
        __syncthreads();
        m0 = fmaxf(pmax[r0],     pmax[64 + r0]);
        m8 = fmaxf(pmax[r0 + 8], pmax[64 + r0 + 8]);

        float s0 = 0.0f, s8 = 0.0f;
#pragma unroll
        for (int nt = 0; nt < 16; ++nt) {
            c[nt][0] = __expf(c[nt][0] - m0);  s0 += c[nt][0];
            c[nt][1] = __expf(c[nt][1] - m0);  s0 += c[nt][1];
            c[nt][2] = __expf(c[nt][2] - m8);  s8 += c[nt][2];
            c[nt][3] = __expf(c[nt][3] - m8);  s8 += c[nt][3];
        }
        s0 += __shfl_xor_sync(0xffffffffu, s0, 1);
        s0 += __shfl_xor_sync(0xffffffffu, s0, 2);
        s8 += __shfl_xor_sync(0xffffffffu, s8, 1);
        s8 += __shfl_xor_sync(0xffffffffu, s8, 2);
        if ((lane & 3) == 0) {
            psum[wn * 64 + r0]     = s0;
            psum[wn * 64 + r0 + 8] = s8;
        }

        float o[8][4];
#pragma unroll
        for (int i = 0; i < 8; ++i)
#pragma unroll
            for (int j = 0; j < 4; ++j) o[i][j] = 0.0f;

#pragma unroll
        for (int kt = 0; kt < 8; ++kt) {
            uint32_t ph[4], pl[4], bh[4][4], bl[4][4];
            {
                const float* ce = c[2 * kt];
                const float* co = c[2 * kt + 1];
                float v[8] = {ce[0], ce[1], ce[2], ce[3], co[0], co[1], co[2], co[3]};
                float h[8], l[8];
#pragma unroll
                for (int j = 0; j < 8; ++j) {
                    __nv_bfloat16 hb = __float2bfloat16(v[j]);
                    h[j] = __bfloat162float(hb);
                    l[j] = v[j] - h[j];
                }
                ph[0] = bf16x2_pack(h[0], h[1]);  ph[1] = bf16x2_pack(h[2], h[3]);
                ph[2] = bf16x2_pack(h[4], h[5]);  ph[3] = bf16x2_pack(h[6], h[7]);
                pl[0] = bf16x2_pack(l[0], l[1]);  pl[1] = bf16x2_pack(l[2], l[3]);
                pl[2] = bf16x2_pack(l[4], l[5]);  pl[3] = bf16x2_pack(l[6], l[7]);
            }
#pragma unroll
            for (int nt2 = 0; nt2 < 4; ++nt2) {
                const int drow = nt2 * 16 + kb_rowc;
                const int kelem = wn * 128 + kt * 16 + kb_ke;
                const uint32_t offV = (uint32_t)(drow * (VSTR * 2) + kelem * 2);
                LDSM_X4(bh[nt2], sb + OFF_VHI + offV);
                LDSM_X4(bl[nt2], sb + OFF_VLO + offV);
            }
#pragma unroll
            for (int nt2 = 0; nt2 < 4; ++nt2) {
                MMA_BF16(o[nt2 * 2 + 0], ph, bh[nt2][0], bh[nt2][1]);
                MMA_BF16(o[nt2 * 2 + 1], ph, bh[nt2][2], bh[nt2][3]);
            }
#pragma unroll
            for (int nt2 = 0; nt2 < 4; ++nt2) {
                MMA_BF16(o[nt2 * 2 + 0], ph, bl[nt2][0], bl[nt2][1]);
                MMA_BF16(o[nt2 * 2 + 1], ph, bl[nt2][2], bl[nt2][3]);
            }
#pragma unroll
            for (int nt2 = 0; nt2 < 4; ++nt2) {
                MMA_BF16(o[nt2 * 2 + 0], pl, bh[nt2][0], bh[nt2][1]);
                MMA_BF16(o[nt2 * 2 + 1], pl, bh[nt2][2], bh[nt2][3]);
            }
        }

        if (wn == 0) {
#pragma unroll
            for (int nt = 0; nt < 8; ++nt) {
                const int cc = nt * 8 + (lane & 3) * 2;
                Osm[r0 * OSTR + cc]           = o[nt][0];
                Osm[r0 * OSTR + cc + 1]       = o[nt][1];
                Osm[(r0 + 8) * OSTR + cc]     = o[nt][2];
                Osm[(r0 + 8) * OSTR + cc + 1] = o[nt][3];
            }
        }
        __syncthreads();
        if (wn == 1) {
#pragma unroll
            for (int nt = 0; nt < 8; ++nt) {
                const int cc = nt * 8 + (lane & 3) * 2;
                Osm[r0 * OSTR + cc]           += o[nt][0];
                Osm[r0 * OSTR + cc + 1]       += o[nt][1];
                Osm[(r0 + 8) * OSTR + cc]     += o[nt][2];
                Osm[(r0 + 8) * OSTR + cc + 1] += o[nt][3];
            }
        }
        __syncthreads();

        {
            const int r = tid >> 2, dg = (tid & 3) * 16;
            const float inv = 1.0f / (psum[r] + psum[64 + r]);
            const size_t gb = (size_t)(tbase + qt * 64 + r) * 512 + head * 64 + dg;
#pragma unroll
            for (int j = 0; j < 16; j += 2) {
                const float v0 = Osm[r * OSTR + dg + j] * inv;
                const float v1 = Osm[r * OSTR + dg + j + 1] * inv;
                const __nv_bfloat16 h0 = __float2bfloat16(v0);
                const __nv_bfloat16 h1 = __float2bfloat16(v1);
                *(__nv_bfloat162*)(ohi + gb + j) = {h0, h1};
                *(__nv_bfloat162*)(olo + gb + j) =
                    {__float2bfloat16(v0 - __bfloat162float(h0)),
                     __float2bfloat16(v1 - __bfloat162float(h1))};
            }
        }
        __syncthreads();
    }
}

// ---------------------------------------------------------------------------
extern "C" void kernel_launch(void* const* d_in, const int* in_sizes, int n_in,
                              void* d_out, int out_size)
{
    const float* x     = (const float*)d_in[0];
    const float* Wqkv  = (const float*)d_in[1];
    const float* bqkv  = (const float*)d_in[2];
    const float* Wproj = (const float*)d_in[3];
    const float* bproj = (const float*)d_in[4];
    const float* abias = (const float*)d_in[5];
    float* out = (float*)d_out;

    __nv_bfloat16 *qkh, *qkl, *xhi, *xlo, *ahi, *alo, *wqhi, *wqlo, *wphi, *wplo;
    cudaGetSymbolAddress((void**)&qkh,  g_qkvhi);
    cudaGetSymbolAddress((void**)&qkl,  g_qkvlo);
    cudaGetSymbolAddress((void**)&xhi,  g_xhi);
    cudaGetSymbolAddress((void**)&xlo,  g_xlo);
    cudaGetSymbolAddress((void**)&ahi,  g_ahi);
    cudaGetSymbolAddress((void**)&alo,  g_alo);
    cudaGetSymbolAddress((void**)&wqhi, g_wqhi);
    cudaGetSymbolAddress((void**)&wqlo, g_wqlo);
    cudaGetSymbolAddress((void**)&wphi, g_wphi);
    cudaGetSymbolAddress((void**)&wplo, g_wplo);

    cudaFuncSetAttribute(gemm_mma, cudaFuncAttributeMaxDynamicSharedMemorySize,
                         GM_SMEM);
    cudaFuncSetAttribute(attn_mma, cudaFuncAttributeMaxDynamicSharedMemorySize,
                         ATT2_SMEM);

    const int n4 = 32768 * 512 / 4;
    split_kernel<<<(n4 + 255) / 256, 256>>>(x, xhi, xlo, n4);
    tsplit_kernel<<<dim3(1536 / 32, 512 / 32), 256>>>(Wqkv, wqhi, wqlo, 512, 1536);
    tsplit_kernel<<<dim3(512 / 32, 512 / 32), 256>>>(Wproj, wphi, wplo, 512, 512);

    gemm_mma<<<NPERSIST, 256, GM_SMEM>>>(xhi, xlo, wqhi, wqlo, bqkv,
                                         nullptr, qkh, qkl, 1536, 32768, 1);
    attn_mma<<<dim3(1024), 256, ATT2_SMEM>>>(qkh, qkl, abias, ahi, alo);
    gemm_mma<<<NPERSIST, 256, GM_SMEM>>>(ahi, alo, wphi, wplo, bproj,
                                         out, nullptr, nullptr, 512, 32768, 0);
}

// round 9
// speedup vs baseline: 1.2840x; 1.2840x over previous
#include <cuda_runtime.h>
#include <cuda_bf16.h>
#include <cuda_fp16.h>
#include <cstdint>

// ---------------------------------------------------------------------------
// b=4, n=8192, dim=512, h=8, w=256, d=64.  T=32768 tokens, 128 windows.
// Round 9 scheme:
//   GEMMs: fp16 2-product split (A single fp16; B = W^T split hi/lo fp16;
//          qkv = A*Bh + A*Bl, error ~ Alo*B ~ 2^-11/sqrt(3) per GEMM).
//   Attention: unchanged bf16 hi/lo 3-product (proven 8.8e-6), but emits
//          fp16 single output for GEMM2.
// ---------------------------------------------------------------------------

__device__ __nv_bfloat16  g_qkvhi[32768ull * 1536], g_qkvlo[32768ull * 1536];
__device__ __half         g_xh[32768ull * 512];
__device__ __half         g_att[32768ull * 512];
__device__ __half         g_wqh[1536ull * 512],  g_wql[1536ull * 512];
__device__ __half         g_wph[512ull * 512],   g_wpl[512ull * 512];

#define NPERSIST 148

// ---------------- helpers ---------------------------------------------------
__device__ __forceinline__ uint32_t smem_u32(const void* p) {
    uint32_t a;
    asm("{ .reg .u64 t; cvta.to.shared.u64 t, %1; cvt.u32.u64 %0, t; }"
        : "=r"(a) : "l"(p));
    return a;
}
#define SWZ128(x) ((x) ^ (((x) >> 3) & 0x70))

__device__ __forceinline__ void cpa16(uint32_t dst, const void* src) {
    asm volatile("cp.async.cg.shared.global [%0], [%1], 16;"
                 :: "r"(dst), "l"(src) : "memory");
}
template <int N>
__device__ __forceinline__ void cp_wait() {
    asm volatile("cp.async.wait_group %0;" :: "n"(N) : "memory");
}

#define LDSM_X4(r, addr)                                                      \
    asm volatile("ldmatrix.sync.aligned.m8n8.x4.shared.b16 {%0,%1,%2,%3}, [%4];" \
                 : "=r"((r)[0]), "=r"((r)[1]), "=r"((r)[2]), "=r"((r)[3])     \
                 : "r"(addr))

#define MMA_BF16(d, a, b0, b1)                                                \
    asm volatile("mma.sync.aligned.m16n8k16.row.col.f32.bf16.bf16.f32 "       \
                 "{%0,%1,%2,%3}, {%4,%5,%6,%7}, {%8,%9}, {%0,%1,%2,%3};"      \
                 : "+f"((d)[0]), "+f"((d)[1]), "+f"((d)[2]), "+f"((d)[3])     \
                 : "r"((a)[0]), "r"((a)[1]), "r"((a)[2]), "r"((a)[3]),        \
                   "r"(b0), "r"(b1))

#define MMA_F16(d, a, b0, b1)                                                 \
    asm volatile("mma.sync.aligned.m16n8k16.row.col.f32.f16.f16.f32 "         \
                 "{%0,%1,%2,%3}, {%4,%5,%6,%7}, {%8,%9}, {%0,%1,%2,%3};"      \
                 : "+f"((d)[0]), "+f"((d)[1]), "+f"((d)[2]), "+f"((d)[3])     \
                 : "r"((a)[0]), "r"((a)[1]), "r"((a)[2]), "r"((a)[3]),        \
                   "r"(b0), "r"(b1))

__device__ __forceinline__ uint32_t bf16x2_pack(float lo, float hi) {
    uint32_t r;
    asm("cvt.rn.bf16x2.f32 %0, %1, %2;" : "=r"(r) : "f"(hi), "f"(lo));
    return r;
}

// ---------------------------------------------------------------------------
// x (fp32) -> fp16 single
// ---------------------------------------------------------------------------
__global__ void tohalf_kernel(const float* __restrict__ in,
                              __half* __restrict__ out, int n4)
{
    int i = blockIdx.x * blockDim.x + threadIdx.x;
    if (i >= n4) return;
    float4 v = ((const float4*)in)[i];
    __half2* op = (__half2*)(out + (size_t)i * 4);
    op[0] = __floats2half2_rn(v.x, v.y);
    op[1] = __floats2half2_rn(v.z, v.w);
}

// ---------------------------------------------------------------------------
// transpose W[K,N] -> Wt[N,K] split into hi/lo fp16
// ---------------------------------------------------------------------------
__global__ void tsplit_kernel(const float* __restrict__ W,
                              __half* __restrict__ thi,
                              __half* __restrict__ tlo, int K, int N)
{
    __shared__ float t[32][33];
    const int kx = blockIdx.y * 32, nx = blockIdx.x * 32;
    const int lx = threadIdx.x & 31, ly = threadIdx.x >> 5;
#pragma unroll
    for (int j = 0; j < 32; j += 8)
        t[ly + j][lx] = W[(size_t)(kx + ly + j) * N + nx + lx];
    __syncthreads();
#pragma unroll
    for (int j = 0; j < 32; j += 8) {
        float v = t[lx][ly + j];
        __half h = __float2half_rn(v);
        __half l = __float2half_rn(v - __half2float(h));
        thi[(size_t)(nx + ly + j) * K + kx + lx] = h;
        tlo[(size_t)(nx + ly + j) * K + kx + lx] = l;
    }
}

// ---------------------------------------------------------------------------
// Persistent fp16 2-product GEMM: C = A[M,512] @ (Bh+Bl)[N,512]^T + bias.
// 256 threads, tile 128x128, warp tile 32x64, 2-stage cp.async, KC=64.
// Stage: A 16KB | Bh 16KB | Bl 16KB = 48KB.
// Per k-group: 10 LDSM.x4, then 32 MMAs grouped A*Bh then A*Bl.
// ---------------------------------------------------------------------------
#define GK        512
#define KC        64
#define CPT       (GK / KC)
#define STAGE     49152
#define GM_SMEM   (2 * STAGE)

__global__ __launch_bounds__(256, 1)
void gemm_mma(const __half* __restrict__ A,
              const __half* __restrict__ Bh,
              const __half* __restrict__ Bl,
              const float* __restrict__ bias,
              float* __restrict__ Cf,
              __nv_bfloat16* __restrict__ Chi, __nv_bfloat16* __restrict__ Clo,
              int N, int M, int bf16out)
{
    extern __shared__ char sm[];
    const uint32_t sb = smem_u32(sm);
    const int tid = threadIdx.x, wid = tid >> 5, lane = tid & 31;
    const int wm = wid & 3, wn = wid >> 2;

    const int gx = N >> 7;
    const int total_tiles = (M >> 7) * gx;
    const int my_tiles = (total_tiles - blockIdx.x + NPERSIST - 1) / NPERSIST;
    const int total_chunks = my_tiles * CPT;

    auto tile_mn = [&](int tl, int& m0, int& n0) {
        const int tg = blockIdx.x + tl * NPERSIST;
        m0 = (tg / gx) << 7;
        n0 = (tg % gx) << 7;
    };

    auto load_ci = [&](int ci) {
        int m0, n0;
        tile_mn(ci >> 3, m0, n0);
        const int k0 = (ci & 7) * KC;
        const uint32_t base = sb + (ci & 1) * STAGE;
#pragma unroll
        for (int it = 0; it < 4; ++it) {
            const int op = it * 256 + tid;
            const int r = op >> 3, g = op & 7;
            const uint32_t off = SWZ128((uint32_t)(r * 128 + g * 16));
            const size_t giA = (size_t)(m0 + r) * GK + k0 + g * 8;
            const size_t giB = (size_t)(n0 + r) * GK + k0 + g * 8;
            cpa16(base + off,         A  + giA);
            cpa16(base + 16384 + off, Bh + giB);
            cpa16(base + 32768 + off, Bl + giB);
        }
        asm volatile("cp.async.commit_group;" ::: "memory");
    };

    float acc[2][8][4];
#pragma unroll
    for (int i = 0; i < 2; ++i)
#pragma unroll
        for (int j = 0; j < 8; ++j)
#pragma unroll
            for (int k = 0; k < 4; ++k) acc[i][j][k] = 0.0f;

    const int a_row = wm * 32 + (lane & 15);
    const int a_kb  = (lane >> 4) * 16;
    const int b_row = wn * 64 + (lane & 7) + ((lane >> 4) << 3);
    const int b_kb  = ((lane >> 3) & 1) * 16;
    const int er = lane >> 2, ec = (lane & 3) * 2;

    if (total_chunks > 0) load_ci(0);
    if (total_chunks > 1) load_ci(1);

    for (int ci = 0; ci < total_chunks; ++ci) {
        if (ci + 1 < total_chunks) cp_wait<1>();
        else                       cp_wait<0>();
        __syncthreads();

        const uint32_t bufb = sb + (ci & 1) * STAGE;
#pragma unroll
        for (int g = 0; g < 4; ++g) {
            uint32_t av[2][4], bh[4][4], bl[4][4];
#pragma unroll
            for (int mt = 0; mt < 2; ++mt) {
                const uint32_t offA =
                    SWZ128((uint32_t)((a_row + mt * 16) * 128 + g * 32 + a_kb));
                LDSM_X4(av[mt], bufb + offA);
            }
#pragma unroll
            for (int np = 0; np < 4; ++np) {
                const uint32_t offB =
                    SWZ128((uint32_t)((b_row + np * 16) * 128 + g * 32 + b_kb));
                LDSM_X4(bh[np], bufb + 16384 + offB);
                LDSM_X4(bl[np], bufb + 32768 + offB);
            }
            // product 1: A * Bh (16 MMAs), then product 2: A * Bl (16 MMAs)
#pragma unroll
            for (int np = 0; np < 4; ++np)
#pragma unroll
                for (int mt = 0; mt < 2; ++mt) {
                    MMA_F16(acc[mt][np * 2 + 0], av[mt], bh[np][0], bh[np][1]);
                    MMA_F16(acc[mt][np * 2 + 1], av[mt], bh[np][2], bh[np][3]);
                }
#pragma unroll
            for (int np = 0; np < 4; ++np)
#pragma unroll
                for (int mt = 0; mt < 2; ++mt) {
                    MMA_F16(acc[mt][np * 2 + 0], av[mt], bl[np][0], bl[np][1]);
                    MMA_F16(acc[mt][np * 2 + 1], av[mt], bl[np][2], bl[np][3]);
                }
        }
        __syncthreads();

        if (ci + 2 < total_chunks) load_ci(ci + 2);

        if ((ci & 7) == 7) {
            int m0, n0;
            tile_mn(ci >> 3, m0, n0);
#pragma unroll
            for (int mt = 0; mt < 2; ++mt) {
                const int row = m0 + wm * 32 + mt * 16 + er;
#pragma unroll
                for (int nt = 0; nt < 8; ++nt) {
                    const int col = n0 + wn * 64 + nt * 8 + ec;
                    const float2 bv = *(const float2*)(bias + col);
                    float v00 = acc[mt][nt][0] + bv.x, v01 = acc[mt][nt][1] + bv.y;
                    float v10 = acc[mt][nt][2] + bv.x, v11 = acc[mt][nt][3] + bv.y;
                    if (bf16out) {
                        __nv_bfloat16 h00 = __float2bfloat16(v00);
                        __nv_bfloat16 h01 = __float2bfloat16(v01);
                        __nv_bfloat16 h10 = __float2bfloat16(v10);
                        __nv_bfloat16 h11 = __float2bfloat16(v11);
                        *(__nv_bfloat162*)(Chi + (size_t)row * N + col)       = {h00, h01};
                        *(__nv_bfloat162*)(Chi + (size_t)(row + 8) * N + col) = {h10, h11};
                        __nv_bfloat162 l0 = {__float2bfloat16(v00 - __bfloat162float(h00)),
                                             __float2bfloat16(v01 - __bfloat162float(h01))};
                        __nv_bfloat162 l1 = {__float2bfloat16(v10 - __bfloat162float(h10)),
                                             __float2bfloat16(v11 - __bfloat162float(h11))};
                        *(__nv_bfloat162*)(Clo + (size_t)row * N + col)       = l0;
                        *(__nv_bfloat162*)(Clo + (size_t)(row + 8) * N + col) = l1;
                    } else {
                        *(float2*)(Cf + (size_t)row * N + col)       = make_float2(v00, v01);
                        *(float2*)(Cf + (size_t)(row + 8) * N + col) = make_float2(v10, v11);
                    }
                    acc[mt][nt][0] = 0.0f; acc[mt][nt][1] = 0.0f;
                    acc[mt][nt][2] = 0.0f; acc[mt][nt][3] = 0.0f;
                }
            }
        }
    }
}

// ---------------------------------------------------------------------------
// Tensor-core block-local attention (bf16 3-product, as round 8), fp16 out.
// ---------------------------------------------------------------------------
#define KSTR 72
#define VSTR 264
#define QSTR 72
#define OSTR 68
#define OFF_KHI  0
#define OFF_KLO  36864
#define OFF_VHI  73728
#define OFF_VLO  107520
#define OFF_QHI  141312
#define OFF_QLO  150528
#define OFF_O    159744
#define OFF_PMAX 177152
#define OFF_PSUM 177664
#define ATT2_SMEM 178176

__global__ __launch_bounds__(256, 1)
void attn_mma(const __nv_bfloat16* __restrict__ qkh,
              const __nv_bfloat16* __restrict__ qkl,
              const float* __restrict__ bias,
              __half* __restrict__ oa)
{
    extern __shared__ char sm[];
    const uint32_t sb = smem_u32(sm);
    float* Osm  = (float*)(sm + OFF_O);
    float* pmax = (float*)(sm + OFF_PMAX);
    float* psum = (float*)(sm + OFF_PSUM);

    const int tid = threadIdx.x, lane = tid & 31, wid = tid >> 5;
    const int wm = wid & 3, wn = wid >> 2;
    const int head = blockIdx.x & 7, win = blockIdx.x >> 3;
    const int tbase = win * 256;
    const float scale = 0.125f;

#pragma unroll
    for (int it = 0; it < 16; ++it) {
        const int idx = it * 256 + tid;
        const int buf = idx >> 11, rem = idx & 2047;
        const int key = rem >> 3, u = rem & 7;
        const __nv_bfloat16* src = (buf ? qkl : qkh) +
            (size_t)(tbase + key) * 1536 + 512 + head * 64 + u * 8;
        char* dst = sm + (buf ? OFF_KLO : OFF_KHI) + key * (KSTR * 2) + u * 16;
        *(uint4*)dst = *(const uint4*)src;
    }
    {
        const int buf = tid >> 7, p = tid & 127;
        const __nv_bfloat16* s0 = (buf ? qkl : qkh) +
            (size_t)(tbase + 2 * p) * 1536 + 1024 + head * 64;
        const __nv_bfloat16* s1 = s0 + 1536;
        char* vt = sm + (buf ? OFF_VLO : OFF_VHI);
#pragma unroll
        for (int u = 0; u < 8; ++u) {
            const uint4 a = *(const uint4*)(s0 + u * 8);
            const uint4 b = *(const uint4*)(s1 + u * 8);
            const unsigned short* ap = (const unsigned short*)&a;
            const unsigned short* bp = (const unsigned short*)&b;
#pragma unroll
            for (int j = 0; j < 8; ++j) {
                const int d = u * 8 + j;
                *(uint32_t*)(vt + d * (VSTR * 2) + p * 4) =
                    (uint32_t)ap[j] | ((uint32_t)bp[j] << 16);
            }
        }
    }
    __syncthreads();

    const int qa_row = wm * 16 + (lane & 15);
    const int qa_ke  = (lane >> 4) * 8;
    const int kb_rowc = (lane & 7) + ((lane >> 4) << 3);
    const int kb_ke   = ((lane >> 3) & 1) * 8;

    for (int qt = 0; qt < 4; ++qt) {
#pragma unroll
        for (int it = 0; it < 4; ++it) {
            const int idx = it * 256 + tid;
            const int buf = idx >> 9, rem = idx & 511;
            const int row = rem >> 3, u = rem & 7;
            const __nv_bfloat16* src = (buf ? qkl : qkh) +
                (size_t)(tbase + qt * 64 + row) * 1536 + head * 64 + u * 8;
            char* dst = sm + (buf ? OFF_QLO : OFF_QHI) + row * (QSTR * 2) + u * 16;
            *(uint4*)dst = *(const uint4*)src;
        }
        __syncthreads();

        float c[16][4];
#pragma unroll
        for (int i = 0; i < 16; ++i)
#pragma unroll
            for (int j = 0; j < 4; ++j) c[i][j] = 0.0f;

#pragma unroll
        for (int kt = 0; kt < 4; ++kt) {
            uint32_t ah[4], al[4], bh[8][4], bl[8][4];
            const uint32_t offQ =
                (uint32_t)(qa_row * (QSTR * 2) + kt * 32 + qa_ke * 2);
            LDSM_X4(ah, sb + OFF_QHI + offQ);
            LDSM_X4(al, sb + OFF_QLO + offQ);
#pragma unroll
            for (int nt2 = 0; nt2 < 8; ++nt2) {
                const int krow = wn * 128 + nt2 * 16 + kb_rowc;
                const uint32_t offK =
                    (uint32_t)(krow * (KSTR * 2) + kt * 32 + kb_ke * 2);
                LDSM_X4(bh[nt2], sb + OFF_KHI + offK);
                LDSM_X4(bl[nt2], sb + OFF_KLO + offK);
            }
#pragma unroll
            for (int nt2 = 0; nt2 < 8; ++nt2) {
                MMA_BF16(c[nt2 * 2 + 0], ah, bh[nt2][0], bh[nt2][1]);
                MMA_BF16(c[nt2 * 2 + 1], ah, bh[nt2][2], bh[nt2][3]);
            }
#pragma unroll
            for (int nt2 = 0; nt2 < 8; ++nt2) {
                MMA_BF16(c[nt2 * 2 + 0], ah, bl[nt2][0], bl[nt2][1]);
                MMA_BF16(c[nt2 * 2 + 1], ah, bl[nt2][2], bl[nt2][3]);
            }
#pragma unroll
            for (int nt2 = 0; nt2 < 8; ++nt2) {
                MMA_BF16(c[nt2 * 2 + 0], al, bh[nt2][0], bh[nt2][1]);
                MMA_BF16(c[nt2 * 2 + 1], al, bh[nt2][2], bh[nt2][3]);
            }
        }

        const float* bb = bias + head * 65536 +
            (size_t)(qt * 64 + wm * 16 + (lane >> 2)) * 256 +
            wn * 128 + (lane & 3) * 2;
#pragma unroll
        for (int nt = 0; nt < 16; ++nt) {
            const float2 b0 = *(const float2*)(bb + nt * 8);
            const float2 b8 = *(const float2*)(bb + 2048 + nt * 8);
            c[nt][0] = c[nt][0] * scale + b0.x;
            c[nt][1] = c[nt][1] * scale + b0.y;
            c[nt][2] = c[nt][2] * scale + b8.x;
            c[nt][3] = c[nt][3] * scale + b8.y;
        }

        float m0 = c[0][0], m8 = c[0][2];
#pragma unroll
        for (int nt = 0; nt < 16; ++nt) {
            m0 = fmaxf(m0, fmaxf(c[nt][0], c[nt][1]));
            m8 = fmaxf(m8, fmaxf(c[nt][2], c[nt][3]));
        }
        m0 = fmaxf(m0, __shfl_xor_sync(0xffffffffu, m0, 1));
        m0 = fmaxf(m0, __shfl_xor_sync(0xffffffffu, m0, 2));
        m8 = fmaxf(m8, __shfl_xor_sync(0xffffffffu, m8, 1));
        m8 = fmaxf(m8, __shfl_xor_sync(0xffffffffu, m8, 2));
        const int r0 = wm * 16 + (lane >> 2);
        if ((lane & 3) == 0) {
            pmax[wn * 64 + r0]     = m0;
            pmax[wn * 64 + r0 + 8] = m8;
        }
        __syncthreads();
        m0 = fmaxf(pmax[r0],     pmax[64 + r0]);
        m8 = fmaxf(pmax[r0 + 8], pmax[64 + r0 + 8]);

        float s0 = 0.0f, s8 = 0.0f;
#pragma unroll
        for (int nt = 0; nt < 16; ++nt) {
            c[nt][0] = __expf(c[nt][0] - m0);  s0 += c[nt][0];
            c[nt][1] = __expf(c[nt][1] - m0);  s0 += c[nt][1];
            c[nt][2] = __expf(c[nt][2] - m8);  s8 += c[nt][2];
            c[nt][3] = __expf(c[nt][3] - m8);  s8 += c[nt][3];
        }
        s0 += __shfl_xor_sync(0xffffffffu, s0, 1);
        s0 += __shfl_xor_sync(0xffffffffu, s0, 2);
        s8 += __shfl_xor_sync(0xffffffffu, s8, 1);
        s8 += __shfl_xor_sync(0xffffffffu, s8, 2);
        if ((lane & 3) == 0) {
            psum[wn * 64 + r0]     = s0;
            psum[wn * 64 + r0 + 8] = s8;
        }

        float o[8][4];
#pragma unroll
        for (int i = 0; i < 8; ++i)
#pragma unroll
            for (int j = 0; j < 4; ++j) o[i][j] = 0.0f;

#pragma unroll
        for (int kt = 0; kt < 8; ++kt) {
            uint32_t ph[4], pl[4], bh[4][4], bl[4][4];
            {
                const float* ce = c[2 * kt];
                const float* co = c[2 * kt + 1];
                float v[8] = {ce[0], ce[1], ce[2], ce[3], co[0], co[1], co[2], co[3]};
                float h[8], l[8];
#pragma unroll
                for (int j = 0; j < 8; ++j) {
                    __nv_bfloat16 hb = __float2bfloat16(v[j]);
                    h[j] = __bfloat162float(hb);
                    l[j] = v[j] - h[j];
                }
                ph[0] = bf16x2_pack(h[0], h[1]);  ph[1] = bf16x2_pack(h[2], h[3]);
                ph[2] = bf16x2_pack(h[4], h[5]);  ph[3] = bf16x2_pack(h[6], h[7]);
                pl[0] = bf16x2_pack(l[0], l[1]);  pl[1] = bf16x2_pack(l[2], l[3]);
                pl[2] = bf16x2_pack(l[4], l[5]);  pl[3] = bf16x2_pack(l[6], l[7]);
            }
#pragma unroll
            for (int nt2 = 0; nt2 < 4; ++nt2) {
                const int drow = nt2 * 16 + kb_rowc;
                const int kelem = wn * 128 + kt * 16 + kb_ke;
                const uint32_t offV = (uint32_t)(drow * (VSTR * 2) + kelem * 2);
                LDSM_X4(bh[nt2], sb + OFF_VHI + offV);
                LDSM_X4(bl[nt2], sb + OFF_VLO + offV);
            }
#pragma unroll
            for (int nt2 = 0; nt2 < 4; ++nt2) {
                MMA_BF16(o[nt2 * 2 + 0], ph, bh[nt2][0], bh[nt2][1]);
                MMA_BF16(o[nt2 * 2 + 1], ph, bh[nt2][2], bh[nt2][3]);
            }
#pragma unroll
            for (int nt2 = 0; nt2 < 4; ++nt2) {
                MMA_BF16(o[nt2 * 2 + 0], ph, bl[nt2][0], bl[nt2][1]);
                MMA_BF16(o[nt2 * 2 + 1], ph, bl[nt2][2], bl[nt2][3]);
            }
#pragma unroll
            for (int nt2 = 0; nt2 < 4; ++nt2) {
                MMA_BF16(o[nt2 * 2 + 0], pl, bh[nt2][0], bh[nt2][1]);
                MMA_BF16(o[nt2 * 2 + 1], pl, bh[nt2][2], bh[nt2][3]);
            }
        }

        if (wn == 0) {
#pragma unroll
            for (int nt = 0; nt < 8; ++nt) {
                const int cc = nt * 8 + (lane & 3) * 2;
                Osm[r0 * OSTR + cc]           = o[nt][0];
                Osm[r0 * OSTR + cc + 1]       = o[nt][1];
                Osm[(r0 + 8) * OSTR + cc]     = o[nt][2];
                Osm[(r0 + 8) * OSTR + cc + 1] = o[nt][3];
            }
        }
        __syncthreads();
        if (wn == 1) {
#pragma unroll
            for (int nt = 0; nt < 8; ++nt) {
                const int cc = nt * 8 + (lane & 3) * 2;
                Osm[r0 * OSTR + cc]           += o[nt][0];
                Osm[r0 * OSTR + cc + 1]       += o[nt][1];
                Osm[(r0 + 8) * OSTR + cc]     += o[nt][2];
                Osm[(r0 + 8) * OSTR + cc + 1] += o[nt][3];
            }
        }
        __syncthreads();

        // ---- normalize + fp16 single store ----
        {
            const int r = tid >> 2, dg = (tid & 3) * 16;
            const float inv = 1.0f / (psum[r] + psum[64 + r]);
            const size_t gb = (size_t)(tbase + qt * 64 + r) * 512 + head * 64 + dg;
#pragma unroll
            for (int j = 0; j < 16; j += 2) {
                const float v0 = Osm[r * OSTR + dg + j] * inv;
                const float v1 = Osm[r * OSTR + dg + j + 1] * inv;
                *(__half2*)(oa + gb + j) = __floats2half2_rn(v0, v1);
            }
        }
        __syncthreads();
    }
}

// ---------------------------------------------------------------------------
extern "C" void kernel_launch(void* const* d_in, const int* in_sizes, int n_in,
                              void* d_out, int out_size)
{
    const float* x     = (const float*)d_in[0];
    const float* Wqkv  = (const float*)d_in[1];
    const float* bqkv  = (const float*)d_in[2];
    const float* Wproj = (const float*)d_in[3];
    const float* bproj = (const float*)d_in[4];
    const float* abias = (const float*)d_in[5];
    float* out = (float*)d_out;

    __nv_bfloat16 *qkh, *qkl;
    __half *xh, *att, *wqh, *wql, *wph, *wpl;
    cudaGetSymbolAddress((void**)&qkh, g_qkvhi);
    cudaGetSymbolAddress((void**)&qkl, g_qkvlo);
    cudaGetSymbolAddress((void**)&xh,  g_xh);
    cudaGetSymbolAddress((void**)&att, g_att);
    cudaGetSymbolAddress((void**)&wqh, g_wqh);
    cudaGetSymbolAddress((void**)&wql, g_wql);
    cudaGetSymbolAddress((void**)&wph, g_wph);
    cudaGetSymbolAddress((void**)&wpl, g_wpl);

    cudaFuncSetAttribute(gemm_mma, cudaFuncAttributeMaxDynamicSharedMemorySize,
                         GM_SMEM);
    cudaFuncSetAttribute(attn_mma, cudaFuncAttributeMaxDynamicSharedMemorySize,
                         ATT2_SMEM);

    const int n4 = 32768 * 512 / 4;
    tohalf_kernel<<<(n4 + 255) / 256, 256>>>(x, xh, n4);
    tsplit_kernel<<<dim3(1536 / 32, 512 / 32), 256>>>(Wqkv, wqh, wql, 512, 1536);
    tsplit_kernel<<<dim3(512 / 32, 512 / 32), 256>>>(Wproj, wph, wpl, 512, 512);

    gemm_mma<<<NPERSIST, 256, GM_SMEM>>>(xh, wqh, wql, bqkv,
                                         nullptr, qkh, qkl, 1536, 32768, 1);
    attn_mma<<<dim3(1024), 256, ATT2_SMEM>>>(qkh, qkl, abias, att);
    gemm_mma<<<NPERSIST, 256, GM_SMEM>>>(att, wph, wpl, bproj,
                                         out, nullptr, nullptr, 512, 32768, 0);
}